// round 2
// baseline (speedup 1.0000x reference)
#include <cuda_runtime.h>

#define BQ   128
#define TQ   1024
#define HQ   256
#define GQ   1024          // 4H
#define INQ  128
#define MROWS (BQ*TQ)      // 131072

// ---------------- scratch (device globals: no allocation allowed) ----------
__device__ float g_xg[(size_t)MROWS * GQ];     // 512 MB: precomputed input gates
__device__ float g_hseq[(size_t)MROWS * HQ];   // 128 MB: per-layer h sequence
__device__ float g_hcur[2][BQ * HQ];           // double-buffered recurrent h
__device__ unsigned int g_bar;                 // grid barrier counter

// ---------------- init: reset barrier + h state ----------------------------
__global__ void init_kernel() {
    int i = blockIdx.x * blockDim.x + threadIdx.x;
    if (i == 0) g_bar = 0u;
    float* p = &g_hcur[0][0];
    for (int k = i; k < 2 * BQ * HQ; k += gridDim.x * blockDim.x) p[k] = 0.f;
}

// ---------------- generic tiled GEMM: C = A(MxK) * Bw(NxK)^T + b1 + b2 -----
__global__ void __launch_bounds__(256, 2) gemm_bias(
    const float* __restrict__ A, const float* __restrict__ Bw,
    const float* __restrict__ b1, const float* __restrict__ b2,
    float* __restrict__ C, int M, int N, int K)
{
    __shared__ float As[16][68];
    __shared__ float Bs[16][68];
    const int tid = threadIdx.x;
    const int tx = tid & 15, ty = tid >> 4;
    const int m0 = blockIdx.y << 6;
    const int n0 = blockIdx.x << 6;
    const int r = tid >> 2, q = tid & 3;

    float acc[4][4];
#pragma unroll
    for (int i = 0; i < 4; ++i)
#pragma unroll
        for (int j = 0; j < 4; ++j) acc[i][j] = 0.f;

    for (int k0 = 0; k0 < K; k0 += 16) {
        float4 av = *(const float4*)&A [(size_t)(m0 + r) * K + k0 + q * 4];
        float4 bv = *(const float4*)&Bw[(size_t)(n0 + r) * K + k0 + q * 4];
        __syncthreads();
        As[q*4+0][r] = av.x; As[q*4+1][r] = av.y; As[q*4+2][r] = av.z; As[q*4+3][r] = av.w;
        Bs[q*4+0][r] = bv.x; Bs[q*4+1][r] = bv.y; Bs[q*4+2][r] = bv.z; Bs[q*4+3][r] = bv.w;
        __syncthreads();
#pragma unroll
        for (int kk = 0; kk < 16; ++kk) {
            float4 a = *(const float4*)&As[kk][ty * 4];
            float4 b = *(const float4*)&Bs[kk][tx * 4];
            acc[0][0] += a.x*b.x; acc[0][1] += a.x*b.y; acc[0][2] += a.x*b.z; acc[0][3] += a.x*b.w;
            acc[1][0] += a.y*b.x; acc[1][1] += a.y*b.y; acc[1][2] += a.y*b.z; acc[1][3] += a.y*b.w;
            acc[2][0] += a.z*b.x; acc[2][1] += a.z*b.y; acc[2][2] += a.z*b.z; acc[2][3] += a.z*b.w;
            acc[3][0] += a.w*b.x; acc[3][1] += a.w*b.y; acc[3][2] += a.w*b.z; acc[3][3] += a.w*b.w;
        }
    }

    const int col = n0 + tx * 4;
    float4 bb = make_float4(0.f, 0.f, 0.f, 0.f);
    if (b1) { float4 t = *(const float4*)&b1[col]; bb.x += t.x; bb.y += t.y; bb.z += t.z; bb.w += t.w; }
    if (b2) { float4 t = *(const float4*)&b2[col]; bb.x += t.x; bb.y += t.y; bb.z += t.z; bb.w += t.w; }
#pragma unroll
    for (int i = 0; i < 4; ++i) {
        int row = m0 + ty * 4 + i;
        float4 r4 = make_float4(acc[i][0] + bb.x, acc[i][1] + bb.y,
                                acc[i][2] + bb.z, acc[i][3] + bb.w);
        *(float4*)&C[(size_t)row * N + col] = r4;
    }
}

// ---------------- persistent recurrent LSTM layer ---------------------------
__device__ __forceinline__ float sigf(float x)  { return 1.f / (1.f + __expf(-x)); }
__device__ __forceinline__ float tanhf_(float x){ return 2.f / (1.f + __expf(-2.f * x)) - 1.f; }

// grid 128 CTAs x 128 threads. CTA = 16 j x 16 b. thread: lane = jl(16) + 16*kc(2),
// warp(4) = b-group of 4. Weights resident in SMEM for the whole kernel.
extern __shared__ float4 s4[];
__global__ void __launch_bounds__(128, 1) lstm_layer(
    const float* __restrict__ xg, const float* __restrict__ whh,
    float* __restrict__ hseq, float* __restrict__ outh, float* __restrict__ outc)
{
    float4* wq = s4;          // [4 gates][64 kq][16 j] float4 = 64 KB
    float4* h4 = s4 + 4096;   // [16 b][64 kq] float4 = 16 KB
    const int tid  = threadIdx.x;
    const int lane = tid & 31;
    const int warp = tid >> 5;           // 0..3
    const int jl   = lane & 15;
    const int kc   = lane >> 4;          // 0/1 : k-split half
    const int j0   = (blockIdx.x & 15) << 4;
    const int b0   = (blockIdx.x >> 4) << 4;
    const int j    = j0 + jl;
    const int bbase = b0 + warp * 4;

    // stage weights once: rows (g*HQ + j0+jj), conflict-free [g][q][jj] layout
    for (int idx = tid; idx < 4096; idx += 128) {
        int g  = idx >> 10;
        int jj = (idx >> 6) & 15;
        int q  = idx & 63;
        float4 v = *(const float4*)(whh + (size_t)(g * HQ + j0 + jj) * HQ + q * 4);
        wq[(g * 64 + q) * 16 + jj] = v;
    }

    float cs[4] = {0.f, 0.f, 0.f, 0.f};
    const int qb = kc * 32;
    const float4* wp = wq + jl;
    const float4* hp = h4 + (warp * 4) * 64;

    for (int t = 0; t < TQ; ++t) {
        const int rbuf = t & 1;
        const int wbuf = rbuf ^ 1;

        // stage h_t for our 16 batches (L2 read: bypass L1 to avoid staleness)
        const float4* hsrc = (const float4*)(&g_hcur[rbuf][b0 * HQ]);
#pragma unroll
        for (int i = 0; i < 8; ++i)
            h4[tid + i * 128] = __ldcg(hsrc + tid + i * 128);

        // prefetch xg_t (hidden under the k-loop)
        float xv[4][4] = {};
        if (kc == 0) {
#pragma unroll
            for (int bi = 0; bi < 4; ++bi) {
                const float* p = xg + ((size_t)(bbase + bi) * TQ + t) * GQ + j;
#pragma unroll
                for (int g = 0; g < 4; ++g) xv[bi][g] = __ldcg(p + g * HQ);
            }
        }
        __syncthreads();

        float acc[4][4];
#pragma unroll
        for (int bi = 0; bi < 4; ++bi)
#pragma unroll
            for (int g = 0; g < 4; ++g) acc[bi][g] = 0.f;

#pragma unroll 8
        for (int qq = 0; qq < 32; ++qq) {
            int q = qb + qq;
            float4 w0 = wp[(0 * 64 + q) * 16];
            float4 w1 = wp[(1 * 64 + q) * 16];
            float4 w2 = wp[(2 * 64 + q) * 16];
            float4 w3 = wp[(3 * 64 + q) * 16];
#pragma unroll
            for (int bi = 0; bi < 4; ++bi) {
                float4 hv = hp[bi * 64 + q];
                acc[bi][0] += w0.x*hv.x + w0.y*hv.y + w0.z*hv.z + w0.w*hv.w;
                acc[bi][1] += w1.x*hv.x + w1.y*hv.y + w1.z*hv.z + w1.w*hv.w;
                acc[bi][2] += w2.x*hv.x + w2.y*hv.y + w2.z*hv.z + w2.w*hv.w;
                acc[bi][3] += w3.x*hv.x + w3.y*hv.y + w3.z*hv.z + w3.w*hv.w;
            }
        }

        // combine the two k-halves
#pragma unroll
        for (int bi = 0; bi < 4; ++bi)
#pragma unroll
            for (int g = 0; g < 4; ++g)
                acc[bi][g] += __shfl_down_sync(0xffffffffu, acc[bi][g], 16);

        if (kc == 0) {
#pragma unroll
            for (int bi = 0; bi < 4; ++bi) {
                float gi = sigf  (acc[bi][0] + xv[bi][0]);
                float gf = sigf  (acc[bi][1] + xv[bi][1]);
                float gg = tanhf_(acc[bi][2] + xv[bi][2]);
                float go = sigf  (acc[bi][3] + xv[bi][3]);
                float cn = gf * cs[bi] + gi * gg;
                cs[bi] = cn;
                float hn = go * tanhf_(cn);
                int b = bbase + bi;
                hseq[((size_t)b * TQ + t) * HQ + j] = hn;
                g_hcur[wbuf][b * HQ + j] = hn;
                if (t == TQ - 1) { outh[b * HQ + j] = hn; outc[b * HQ + j] = cn; }
            }
        }

        // grid barrier (sense-free monotone counter, reset per launch)
        __threadfence();
        __syncthreads();
        if (tid == 0) {
            atomicAdd(&g_bar, 1u);
            unsigned target = (unsigned)gridDim.x * (unsigned)(t + 1);
            while (*((volatile unsigned int*)&g_bar) < target) { }
        }
        __syncthreads();
    }
}

// ---------------- launch -----------------------------------------------------
#define LSTM_SMEM ((4096 + 1024) * 16)

extern "C" void kernel_launch(void* const* d_in, const int* in_sizes, int n_in,
                              void* d_out, int out_size)
{
    const float* x    = (const float*)d_in[0];
    const float* wih0 = (const float*)d_in[1];
    const float* whh0 = (const float*)d_in[2];
    const float* bih0 = (const float*)d_in[3];
    const float* bhh0 = (const float*)d_in[4];
    const float* wih1 = (const float*)d_in[5];
    const float* whh1 = (const float*)d_in[6];
    const float* bih1 = (const float*)d_in[7];
    const float* bhh1 = (const float*)d_in[8];
    const float* wlin = (const float*)d_in[9];
    const float* blin = (const float*)d_in[10];

    float* out  = (float*)d_out;                    // [B,T,In]
    float* outh = out + (size_t)BQ * TQ * INQ;      // [2,B,H]
    float* outc = outh + 2 * BQ * HQ;               // [2,B,H]

    float *p_xg, *p_hseq;
    cudaGetSymbolAddress((void**)&p_xg,   g_xg);
    cudaGetSymbolAddress((void**)&p_hseq, g_hseq);
    cudaFuncSetAttribute(lstm_layer, cudaFuncAttributeMaxDynamicSharedMemorySize, LSTM_SMEM);

    dim3 gg(GQ / 64, MROWS / 64);
    dim3 gf(INQ / 64, MROWS / 64);

    // layer 0
    init_kernel<<<64, 256>>>();
    gemm_bias<<<gg, 256>>>(x, wih0, bih0, bhh0, p_xg, MROWS, GQ, INQ);
    lstm_layer<<<128, 128, LSTM_SMEM>>>(p_xg, whh0, p_hseq, outh, outc);
    // layer 1
    init_kernel<<<64, 256>>>();
    gemm_bias<<<gg, 256>>>(p_hseq, wih1, bih1, bhh1, p_xg, MROWS, GQ, HQ);
    lstm_layer<<<128, 128, LSTM_SMEM>>>(p_xg, whh1, p_hseq, outh + BQ * HQ, outc + BQ * HQ);
    // final projection
    gemm_bias<<<gf, 256>>>(p_hseq, wlin, blin, nullptr, out, MROWS, INQ, HQ);
}

// round 3
// speedup vs baseline: 1.0768x; 1.0768x over previous
#include <cuda_runtime.h>
#include <cuda_bf16.h>

#define BQ   128
#define TQ   1024
#define HQ   256
#define GQ   1024          // 4H
#define INQ  128
#define MROWS (BQ*TQ)      // 131072

// ---------------- scratch (device globals: no allocation allowed) ----------
__device__ float g_xg[(size_t)MROWS * GQ];     // 512 MB: precomputed input gates
__device__ float g_hseq[(size_t)MROWS * HQ];   // 128 MB: per-layer h sequence
__device__ float g_hcur[2][BQ * HQ];           // double-buffered recurrent h
__device__ unsigned int g_bar;                 // grid barrier counter

extern __shared__ float4 s4[];

// ---------------- init: reset barrier + h state ----------------------------
__global__ void init_kernel() {
    int i = blockIdx.x * blockDim.x + threadIdx.x;
    if (i == 0) g_bar = 0u;
    float* p = &g_hcur[0][0];
    for (int k = i; k < 2 * BQ * HQ; k += gridDim.x * blockDim.x) p[k] = 0.f;
}

// ============================================================================
// Tensor-core GEMM: C = A(MxK) * Bw(NxK)^T + b1 + b2   (fp32 in/out)
// 3-term bf16 split: A=Ah+Al, B=Bh+Bl; C += Ah*Bh + Ah*Bl + Al*Bh (fp32 acc)
// CTA tile 128x128, K-step 64. 256 threads = 8 warps (4 m-warps x 2 n-warps),
// warp tile 32x64. SW128-style swizzle for conflict-free ldmatrix.
// ============================================================================

__device__ __forceinline__ void mma16816(float* d, const unsigned* a,
                                         unsigned b0, unsigned b1) {
    asm volatile(
        "mma.sync.aligned.m16n8k16.row.col.f32.bf16.bf16.f32 "
        "{%0,%1,%2,%3}, {%4,%5,%6,%7}, {%8,%9}, {%0,%1,%2,%3};\n"
        : "+f"(d[0]), "+f"(d[1]), "+f"(d[2]), "+f"(d[3])
        : "r"(a[0]), "r"(a[1]), "r"(a[2]), "r"(a[3]), "r"(b0), "r"(b1));
}

__device__ __forceinline__ void ldsm4(unsigned* r, unsigned addr) {
    asm volatile(
        "ldmatrix.sync.aligned.m8n8.x4.shared.b16 {%0,%1,%2,%3}, [%4];\n"
        : "=r"(r[0]), "=r"(r[1]), "=r"(r[2]), "=r"(r[3]) : "r"(addr));
}

// bf16 element (row, k) inside a 128x64 tile: 128B rows, 16B chunks xor row&7
__device__ __forceinline__ unsigned sw_off(int row, int k) {
    return (unsigned)(row * 128 + ((((k >> 3) ^ row) & 7) << 4) + ((k & 7) << 1));
}

#define TILE_B 16384   // bytes per bf16 128x64 tile

__global__ void __launch_bounds__(256) gemm3bf16(
    const float* __restrict__ A, const float* __restrict__ Bw,
    const float* __restrict__ b1, const float* __restrict__ b2,
    float* __restrict__ C, int M, int N, int K)
{
    char* sm = (char*)s4;
    // tiles: Ah | Al | Bh | Bl
    unsigned sbase = (unsigned)__cvta_generic_to_shared(sm);

    const int tid  = threadIdx.x;
    const int lane = tid & 31;
    const int warp = tid >> 5;
    const int wm   = warp & 3;    // m-warp: 32 rows
    const int wn   = warp >> 2;   // n-warp: 64 cols
    const int m0   = blockIdx.y << 7;
    const int n0   = blockIdx.x << 7;

    // global load mapping: row = tid>>1 (128 rows), half = tid&1 (32 floats)
    const int grow = tid >> 1;
    const int gkb  = (tid & 1) * 32;

    float acc[2][8][4];
#pragma unroll
    for (int mt = 0; mt < 2; ++mt)
#pragma unroll
        for (int nt = 0; nt < 8; ++nt)
#pragma unroll
            for (int e = 0; e < 4; ++e) acc[mt][nt][e] = 0.f;

    const float* pA = A + (size_t)(m0 + grow) * K + gkb;
    const float* pB = Bw + (size_t)(n0 + grow) * K + gkb;

    float4 va[8], vb[8];
#pragma unroll
    for (int i = 0; i < 8; ++i) { va[i] = *(const float4*)(pA + i * 4); }
#pragma unroll
    for (int i = 0; i < 8; ++i) { vb[i] = *(const float4*)(pB + i * 4); }

    for (int k0 = 0; k0 < K; k0 += 64) {
        __syncthreads();   // previous compute done; smem free

        // convert + swizzled store (pairs of adjacent k share a 16B chunk)
#pragma unroll
        for (int i = 0; i < 8; ++i) {
            float f[4] = {va[i].x, va[i].y, va[i].z, va[i].w};
            __nv_bfloat16 h[4]; float r[4];
#pragma unroll
            for (int e = 0; e < 4; ++e) {
                h[e] = __float2bfloat16_rn(f[e]);
                r[e] = f[e] - __bfloat162float(h[e]);
            }
            int kk = gkb + i * 4;
            unsigned o0 = sbase + sw_off(grow, kk);
            unsigned o1 = sbase + sw_off(grow, kk + 2);
            unsigned hi01, hi23, lo01, lo23;
            __nv_bfloat162 t;
            t = __nv_bfloat162(h[0], h[1]); hi01 = *(unsigned*)&t;
            t = __nv_bfloat162(h[2], h[3]); hi23 = *(unsigned*)&t;
            t = __nv_bfloat162(__float2bfloat16_rn(r[0]), __float2bfloat16_rn(r[1])); lo01 = *(unsigned*)&t;
            t = __nv_bfloat162(__float2bfloat16_rn(r[2]), __float2bfloat16_rn(r[3])); lo23 = *(unsigned*)&t;
            asm volatile("st.shared.b32 [%0], %1;\n" :: "r"(o0), "r"(hi01));
            asm volatile("st.shared.b32 [%0], %1;\n" :: "r"(o1), "r"(hi23));
            asm volatile("st.shared.b32 [%0], %1;\n" :: "r"(o0 + TILE_B), "r"(lo01));
            asm volatile("st.shared.b32 [%0], %1;\n" :: "r"(o1 + TILE_B), "r"(lo23));
        }
#pragma unroll
        for (int i = 0; i < 8; ++i) {
            float f[4] = {vb[i].x, vb[i].y, vb[i].z, vb[i].w};
            __nv_bfloat16 h[4]; float r[4];
#pragma unroll
            for (int e = 0; e < 4; ++e) {
                h[e] = __float2bfloat16_rn(f[e]);
                r[e] = f[e] - __bfloat162float(h[e]);
            }
            int kk = gkb + i * 4;
            unsigned o0 = sbase + 2 * TILE_B + sw_off(grow, kk);
            unsigned o1 = sbase + 2 * TILE_B + sw_off(grow, kk + 2);
            unsigned hi01, hi23, lo01, lo23;
            __nv_bfloat162 t;
            t = __nv_bfloat162(h[0], h[1]); hi01 = *(unsigned*)&t;
            t = __nv_bfloat162(h[2], h[3]); hi23 = *(unsigned*)&t;
            t = __nv_bfloat162(__float2bfloat16_rn(r[0]), __float2bfloat16_rn(r[1])); lo01 = *(unsigned*)&t;
            t = __nv_bfloat162(__float2bfloat16_rn(r[2]), __float2bfloat16_rn(r[3])); lo23 = *(unsigned*)&t;
            asm volatile("st.shared.b32 [%0], %1;\n" :: "r"(o0), "r"(hi01));
            asm volatile("st.shared.b32 [%0], %1;\n" :: "r"(o1), "r"(hi23));
            asm volatile("st.shared.b32 [%0], %1;\n" :: "r"(o0 + TILE_B), "r"(lo01));
            asm volatile("st.shared.b32 [%0], %1;\n" :: "r"(o1 + TILE_B), "r"(lo23));
        }
        __syncthreads();

        // prefetch next k-slab while tensor cores chew on this one
        if (k0 + 64 < K) {
#pragma unroll
            for (int i = 0; i < 8; ++i) va[i] = *(const float4*)(pA + k0 + 64 + i * 4);
#pragma unroll
            for (int i = 0; i < 8; ++i) vb[i] = *(const float4*)(pB + k0 + 64 + i * 4);
        }

#pragma unroll
        for (int k16 = 0; k16 < 64; k16 += 16) {
            unsigned ah[2][4], al[2][4];
#pragma unroll
            for (int mt = 0; mt < 2; ++mt) {
                int row = wm * 32 + mt * 16 + (lane & 15);
                int kk  = k16 + ((lane >> 4) << 3);
                unsigned ad = sbase + sw_off(row, kk);
                ldsm4(ah[mt], ad);
                ldsm4(al[mt], ad + TILE_B);
            }
#pragma unroll
            for (int g = 0; g < 4; ++g) {
                unsigned bh[4], bl[4];
                int row = wn * 64 + g * 16 + (lane & 15);
                int kk  = k16 + ((lane >> 4) << 3);
                unsigned bd = sbase + 2 * TILE_B + sw_off(row, kk);
                ldsm4(bh, bd);
                ldsm4(bl, bd + TILE_B);
#pragma unroll
                for (int mt = 0; mt < 2; ++mt) {
                    // n8 tile (2g): b regs {r0,r2}; tile (2g+1): {r1,r3}
                    mma16816(acc[mt][2 * g],     ah[mt], bh[0], bh[2]);
                    mma16816(acc[mt][2 * g],     ah[mt], bl[0], bl[2]);
                    mma16816(acc[mt][2 * g],     al[mt], bh[0], bh[2]);
                    mma16816(acc[mt][2 * g + 1], ah[mt], bh[1], bh[3]);
                    mma16816(acc[mt][2 * g + 1], ah[mt], bl[1], bl[3]);
                    mma16816(acc[mt][2 * g + 1], al[mt], bh[1], bh[3]);
                }
            }
        }
    }

    // epilogue: add bias, store fp32
#pragma unroll
    for (int nt = 0; nt < 8; ++nt) {
        int col = n0 + wn * 64 + nt * 8 + ((lane & 3) << 1);
        float bx = 0.f, by = 0.f;
        if (b1) { float2 t = *(const float2*)&b1[col]; bx += t.x; by += t.y; }
        if (b2) { float2 t = *(const float2*)&b2[col]; bx += t.x; by += t.y; }
#pragma unroll
        for (int mt = 0; mt < 2; ++mt) {
            int row = m0 + wm * 32 + mt * 16 + (lane >> 2);
            float2 c0 = make_float2(acc[mt][nt][0] + bx, acc[mt][nt][1] + by);
            float2 c1 = make_float2(acc[mt][nt][2] + bx, acc[mt][nt][3] + by);
            *(float2*)&C[(size_t)row * N + col] = c0;
            *(float2*)&C[(size_t)(row + 8) * N + col] = c1;
        }
    }
}

// ---------------- persistent recurrent LSTM layer (unchanged) ---------------
__device__ __forceinline__ float sigf(float x)  { return 1.f / (1.f + __expf(-x)); }
__device__ __forceinline__ float tanhf_(float x){ return 2.f / (1.f + __expf(-2.f * x)) - 1.f; }

__global__ void __launch_bounds__(128, 1) lstm_layer(
    const float* __restrict__ xg, const float* __restrict__ whh,
    float* __restrict__ hseq, float* __restrict__ outh, float* __restrict__ outc)
{
    float4* wq = s4;          // [4 gates][64 kq][16 j] float4 = 64 KB
    float4* h4 = s4 + 4096;   // [16 b][64 kq] float4 = 16 KB
    const int tid  = threadIdx.x;
    const int lane = tid & 31;
    const int warp = tid >> 5;           // 0..3
    const int jl   = lane & 15;
    const int kc   = lane >> 4;          // 0/1 : k-split half
    const int j0   = (blockIdx.x & 15) << 4;
    const int b0   = (blockIdx.x >> 4) << 4;
    const int j    = j0 + jl;
    const int bbase = b0 + warp * 4;

    for (int idx = tid; idx < 4096; idx += 128) {
        int g  = idx >> 10;
        int jj = (idx >> 6) & 15;
        int q  = idx & 63;
        float4 v = *(const float4*)(whh + (size_t)(g * HQ + j0 + jj) * HQ + q * 4);
        wq[(g * 64 + q) * 16 + jj] = v;
    }

    float cs[4] = {0.f, 0.f, 0.f, 0.f};
    const int qb = kc * 32;
    const float4* wp = wq + jl;
    const float4* hp = h4 + (warp * 4) * 64;

    for (int t = 0; t < TQ; ++t) {
        const int rbuf = t & 1;
        const int wbuf = rbuf ^ 1;

        const float4* hsrc = (const float4*)(&g_hcur[rbuf][b0 * HQ]);
#pragma unroll
        for (int i = 0; i < 8; ++i)
            h4[tid + i * 128] = __ldcg(hsrc + tid + i * 128);

        float xv[4][4] = {};
        if (kc == 0) {
#pragma unroll
            for (int bi = 0; bi < 4; ++bi) {
                const float* p = xg + ((size_t)(bbase + bi) * TQ + t) * GQ + j;
#pragma unroll
                for (int g = 0; g < 4; ++g) xv[bi][g] = __ldcg(p + g * HQ);
            }
        }
        __syncthreads();

        float acc[4][4];
#pragma unroll
        for (int bi = 0; bi < 4; ++bi)
#pragma unroll
            for (int g = 0; g < 4; ++g) acc[bi][g] = 0.f;

#pragma unroll 8
        for (int qq = 0; qq < 32; ++qq) {
            int q = qb + qq;
            float4 w0 = wp[(0 * 64 + q) * 16];
            float4 w1 = wp[(1 * 64 + q) * 16];
            float4 w2 = wp[(2 * 64 + q) * 16];
            float4 w3 = wp[(3 * 64 + q) * 16];
#pragma unroll
            for (int bi = 0; bi < 4; ++bi) {
                float4 hv = hp[bi * 64 + q];
                acc[bi][0] += w0.x*hv.x + w0.y*hv.y + w0.z*hv.z + w0.w*hv.w;
                acc[bi][1] += w1.x*hv.x + w1.y*hv.y + w1.z*hv.z + w1.w*hv.w;
                acc[bi][2] += w2.x*hv.x + w2.y*hv.y + w2.z*hv.z + w2.w*hv.w;
                acc[bi][3] += w3.x*hv.x + w3.y*hv.y + w3.z*hv.z + w3.w*hv.w;
            }
        }

#pragma unroll
        for (int bi = 0; bi < 4; ++bi)
#pragma unroll
            for (int g = 0; g < 4; ++g)
                acc[bi][g] += __shfl_down_sync(0xffffffffu, acc[bi][g], 16);

        if (kc == 0) {
#pragma unroll
            for (int bi = 0; bi < 4; ++bi) {
                float gi = sigf  (acc[bi][0] + xv[bi][0]);
                float gf = sigf  (acc[bi][1] + xv[bi][1]);
                float gg = tanhf_(acc[bi][2] + xv[bi][2]);
                float go = sigf  (acc[bi][3] + xv[bi][3]);
                float cn = gf * cs[bi] + gi * gg;
                cs[bi] = cn;
                float hn = go * tanhf_(cn);
                int b = bbase + bi;
                hseq[((size_t)b * TQ + t) * HQ + j] = hn;
                g_hcur[wbuf][b * HQ + j] = hn;
                if (t == TQ - 1) { outh[b * HQ + j] = hn; outc[b * HQ + j] = cn; }
            }
        }

        __threadfence();
        __syncthreads();
        if (tid == 0) {
            atomicAdd(&g_bar, 1u);
            unsigned target = (unsigned)gridDim.x * (unsigned)(t + 1);
            while (*((volatile unsigned int*)&g_bar) < target) { }
        }
        __syncthreads();
    }
}

// ---------------- launch -----------------------------------------------------
#define LSTM_SMEM ((4096 + 1024) * 16)
#define GEMM_SMEM (4 * TILE_B)

extern "C" void kernel_launch(void* const* d_in, const int* in_sizes, int n_in,
                              void* d_out, int out_size)
{
    const float* x    = (const float*)d_in[0];
    const float* wih0 = (const float*)d_in[1];
    const float* whh0 = (const float*)d_in[2];
    const float* bih0 = (const float*)d_in[3];
    const float* bhh0 = (const float*)d_in[4];
    const float* wih1 = (const float*)d_in[5];
    const float* whh1 = (const float*)d_in[6];
    const float* bih1 = (const float*)d_in[7];
    const float* bhh1 = (const float*)d_in[8];
    const float* wlin = (const float*)d_in[9];
    const float* blin = (const float*)d_in[10];

    float* out  = (float*)d_out;                    // [B,T,In]
    float* outh = out + (size_t)BQ * TQ * INQ;      // [2,B,H]
    float* outc = outh + 2 * BQ * HQ;               // [2,B,H]

    float *p_xg, *p_hseq;
    cudaGetSymbolAddress((void**)&p_xg,   g_xg);
    cudaGetSymbolAddress((void**)&p_hseq, g_hseq);
    cudaFuncSetAttribute(lstm_layer, cudaFuncAttributeMaxDynamicSharedMemorySize, LSTM_SMEM);
    cudaFuncSetAttribute(gemm3bf16, cudaFuncAttributeMaxDynamicSharedMemorySize, GEMM_SMEM);

    dim3 gg(GQ / 128, MROWS / 128);    // (8, 1024)
    dim3 gf(INQ / 128, MROWS / 128);   // (1, 1024)

    // layer 0
    init_kernel<<<64, 256>>>();
    gemm3bf16<<<gg, 256, GEMM_SMEM>>>(x, wih0, bih0, bhh0, p_xg, MROWS, GQ, INQ);
    lstm_layer<<<128, 128, LSTM_SMEM>>>(p_xg, whh0, p_hseq, outh, outc);
    // layer 1
    init_kernel<<<64, 256>>>();
    gemm3bf16<<<gg, 256, GEMM_SMEM>>>(p_hseq, wih1, bih1, bhh1, p_xg, MROWS, GQ, HQ);
    lstm_layer<<<128, 128, LSTM_SMEM>>>(p_xg, whh1, p_hseq, outh + BQ * HQ, outc + BQ * HQ);
    // final projection
    gemm3bf16<<<gf, 256, GEMM_SMEM>>>(p_hseq, wlin, blin, nullptr, out, MROWS, INQ, HQ);
}

// round 5
// speedup vs baseline: 1.2989x; 1.2063x over previous
#include <cuda_runtime.h>
#include <cuda_bf16.h>
#include <cstdint>

#define BQ   128
#define TQ   1024
#define HQ   256
#define GQ   1024          // 4H
#define INQ  128
#define MROWS (BQ*TQ)      // 131072

// ---------------- scratch (device globals: no allocation allowed) ----------
__device__ float g_xg[(size_t)MROWS * GQ];     // 512 MB: precomputed input gates
__device__ float g_hseq[(size_t)MROWS * HQ];   // 128 MB: per-layer h sequence
__device__ float g_hcur[2][BQ * HQ];           // double-buffered recurrent h
__device__ unsigned int g_bar;                 // grid barrier counter

extern __shared__ float4 s4[];

// ---------------- init: reset barrier + h state ----------------------------
__global__ void init_kernel() {
    int i = blockIdx.x * blockDim.x + threadIdx.x;
    if (i == 0) g_bar = 0u;
    float* p = &g_hcur[0][0];
    for (int k = i; k < 2 * BQ * HQ; k += gridDim.x * blockDim.x) p[k] = 0.f;
}

// ---------------- shared helpers -------------------------------------------
__device__ __forceinline__ void mma16816(float* d, const unsigned* a,
                                         unsigned b0, unsigned b1) {
    asm volatile(
        "mma.sync.aligned.m16n8k16.row.col.f32.bf16.bf16.f32 "
        "{%0,%1,%2,%3}, {%4,%5,%6,%7}, {%8,%9}, {%0,%1,%2,%3};\n"
        : "+f"(d[0]), "+f"(d[1]), "+f"(d[2]), "+f"(d[3])
        : "r"(a[0]), "r"(a[1]), "r"(a[2]), "r"(a[3]), "r"(b0), "r"(b1));
}

__device__ __forceinline__ void ldsm4(unsigned* r, unsigned addr) {
    asm volatile(
        "ldmatrix.sync.aligned.m8n8.x4.shared.b16 {%0,%1,%2,%3}, [%4];\n"
        : "=r"(r[0]), "=r"(r[1]), "=r"(r[2]), "=r"(r[3]) : "r"(addr));
}

// bf16 element (row, k) inside a rows x 64k tile: 128B rows, 16B chunks xor row&7
__device__ __forceinline__ unsigned sw_off(int row, int k) {
    return (unsigned)(row * 128 + ((((k >> 3) ^ row) & 7) << 4) + ((k & 7) << 1));
}

__device__ __forceinline__ unsigned pk2(float a, float b) {
    __nv_bfloat162 t(__float2bfloat16_rn(a), __float2bfloat16_rn(b));
    return *(unsigned*)&t;
}

__device__ __forceinline__ void stsv2(unsigned addr, unsigned a, unsigned b) {
    asm volatile("st.shared.v2.b32 [%0], {%1,%2};\n" :: "r"(addr), "r"(a), "r"(b));
}

__device__ __forceinline__ float sigf(float x)   { return 1.f / (1.f + __expf(-x)); }
__device__ __forceinline__ float tanhf_(float x) { return 2.f / (1.f + __expf(-2.f * x)) - 1.f; }

// ============================================================================
// Feedforward tensor GEMM (validated R3): C = A(MxK)*Bw(NxK)^T + b1 + b2
// ============================================================================
#define TILE_B 16384   // bytes per bf16 128x64 tile

__global__ void __launch_bounds__(256) gemm3bf16(
    const float* __restrict__ A, const float* __restrict__ Bw,
    const float* __restrict__ b1, const float* __restrict__ b2,
    float* __restrict__ C, int M, int N, int K)
{
    char* sm = (char*)s4;
    unsigned sbase = (unsigned)__cvta_generic_to_shared(sm);

    const int tid  = threadIdx.x;
    const int lane = tid & 31;
    const int warp = tid >> 5;
    const int wm   = warp & 3;
    const int wn   = warp >> 2;
    const int m0   = blockIdx.y << 7;
    const int n0   = blockIdx.x << 7;

    const int grow = tid >> 1;
    const int gkb  = (tid & 1) * 32;

    float acc[2][8][4];
#pragma unroll
    for (int mt = 0; mt < 2; ++mt)
#pragma unroll
        for (int nt = 0; nt < 8; ++nt)
#pragma unroll
            for (int e = 0; e < 4; ++e) acc[mt][nt][e] = 0.f;

    const float* pA = A + (size_t)(m0 + grow) * K + gkb;
    const float* pB = Bw + (size_t)(n0 + grow) * K + gkb;

    float4 va[8], vb[8];
#pragma unroll
    for (int i = 0; i < 8; ++i) { va[i] = *(const float4*)(pA + i * 4); }
#pragma unroll
    for (int i = 0; i < 8; ++i) { vb[i] = *(const float4*)(pB + i * 4); }

    for (int k0 = 0; k0 < K; k0 += 64) {
        __syncthreads();
#pragma unroll
        for (int i = 0; i < 8; ++i) {
            float f[4] = {va[i].x, va[i].y, va[i].z, va[i].w};
            __nv_bfloat16 h[4]; float r[4];
#pragma unroll
            for (int e = 0; e < 4; ++e) {
                h[e] = __float2bfloat16_rn(f[e]);
                r[e] = f[e] - __bfloat162float(h[e]);
            }
            int kk = gkb + i * 4;
            unsigned o0 = sbase + sw_off(grow, kk);
            __nv_bfloat162 t;
            unsigned hi01; t = __nv_bfloat162(h[0], h[1]); hi01 = *(unsigned*)&t;
            unsigned hi23; t = __nv_bfloat162(h[2], h[3]); hi23 = *(unsigned*)&t;
            stsv2(o0, hi01, hi23);
            stsv2(o0 + TILE_B, pk2(r[0], r[1]), pk2(r[2], r[3]));
        }
#pragma unroll
        for (int i = 0; i < 8; ++i) {
            float f[4] = {vb[i].x, vb[i].y, vb[i].z, vb[i].w};
            __nv_bfloat16 h[4]; float r[4];
#pragma unroll
            for (int e = 0; e < 4; ++e) {
                h[e] = __float2bfloat16_rn(f[e]);
                r[e] = f[e] - __bfloat162float(h[e]);
            }
            int kk = gkb + i * 4;
            unsigned o0 = sbase + 2 * TILE_B + sw_off(grow, kk);
            __nv_bfloat162 t;
            unsigned hi01; t = __nv_bfloat162(h[0], h[1]); hi01 = *(unsigned*)&t;
            unsigned hi23; t = __nv_bfloat162(h[2], h[3]); hi23 = *(unsigned*)&t;
            stsv2(o0, hi01, hi23);
            stsv2(o0 + TILE_B, pk2(r[0], r[1]), pk2(r[2], r[3]));
        }
        __syncthreads();

        if (k0 + 64 < K) {
#pragma unroll
            for (int i = 0; i < 8; ++i) va[i] = *(const float4*)(pA + k0 + 64 + i * 4);
#pragma unroll
            for (int i = 0; i < 8; ++i) vb[i] = *(const float4*)(pB + k0 + 64 + i * 4);
        }

#pragma unroll
        for (int k16 = 0; k16 < 64; k16 += 16) {
            unsigned ah[2][4], al[2][4];
#pragma unroll
            for (int mt = 0; mt < 2; ++mt) {
                int row = wm * 32 + mt * 16 + (lane & 15);
                int kk  = k16 + ((lane >> 4) << 3);
                unsigned ad = sbase + sw_off(row, kk);
                ldsm4(ah[mt], ad);
                ldsm4(al[mt], ad + TILE_B);
            }
#pragma unroll
            for (int g = 0; g < 4; ++g) {
                unsigned bh[4], bl[4];
                int row = wn * 64 + g * 16 + (lane & 15);
                int kk  = k16 + ((lane >> 4) << 3);
                unsigned bd = sbase + 2 * TILE_B + sw_off(row, kk);
                ldsm4(bh, bd);
                ldsm4(bl, bd + TILE_B);
#pragma unroll
                for (int mt = 0; mt < 2; ++mt) {
                    mma16816(acc[mt][2 * g],     ah[mt], bh[0], bh[2]);
                    mma16816(acc[mt][2 * g],     ah[mt], bl[0], bl[2]);
                    mma16816(acc[mt][2 * g],     al[mt], bh[0], bh[2]);
                    mma16816(acc[mt][2 * g + 1], ah[mt], bh[1], bh[3]);
                    mma16816(acc[mt][2 * g + 1], ah[mt], bl[1], bl[3]);
                    mma16816(acc[mt][2 * g + 1], al[mt], bh[1], bh[3]);
                }
            }
        }
    }

#pragma unroll
    for (int nt = 0; nt < 8; ++nt) {
        int col = n0 + wn * 64 + nt * 8 + ((lane & 3) << 1);
        float bx = 0.f, by = 0.f;
        if (b1) { float2 t = *(const float2*)&b1[col]; bx += t.x; by += t.y; }
        if (b2) { float2 t = *(const float2*)&b2[col]; bx += t.x; by += t.y; }
#pragma unroll
        for (int mt = 0; mt < 2; ++mt) {
            int row = m0 + wm * 32 + mt * 16 + (lane >> 2);
            float2 c0 = make_float2(acc[mt][nt][0] + bx, acc[mt][nt][1] + by);
            float2 c1 = make_float2(acc[mt][nt][2] + bx, acc[mt][nt][3] + by);
            *(float2*)&C[(size_t)row * N + col] = c0;
            *(float2*)&C[(size_t)(row + 8) * N + col] = c1;
        }
    }
}

// ============================================================================
// Recurrent layer on mma.sync: 128 CTAs (16 j-chunks x 8 b-chunks).
// Per CTA: D[64 gate-rows x 16 batches], K=256, 3-term bf16 hi/lo split.
// W resident in SMEM (staged once). Grid barrier per step.
// ============================================================================
#define LJ 16
#define LB 16
#define LGRID 128

// smem byte offsets
#define MO_AHI 0                       // A hi: 4 slabs of 64x64 bf16 (8KB) = 32KB
#define MO_ALO 32768                   // A lo: 32KB
#define MO_BHI 65536                   // B hi: 4 slabs of 16x64 bf16 (2KB) = 8KB
#define MO_BLO (65536 + 8192)          // B lo: 8KB
#define MO_GB  (65536 + 16384)         // gate buf: 64 x 18 floats = 4608B
#define LSTM_SMEM_MMA (MO_GB + 64*18*4 + 64)

__device__ __forceinline__ unsigned aw_off(int row, int k) {
    return (unsigned)((k >> 6) * 8192) + sw_off(row, k & 63);
}
__device__ __forceinline__ unsigned bw_off(int row, int k) {
    return (unsigned)((k >> 6) * 2048) + sw_off(row, k & 63);
}

__global__ void __launch_bounds__(128, 1) lstm_mma(
    const float* __restrict__ xg, const float* __restrict__ whh,
    float* __restrict__ hseq, float* __restrict__ outh, float* __restrict__ outc)
{
    char* sm = (char*)s4;
    unsigned sb = (unsigned)__cvta_generic_to_shared(sm);
    float* gb = (float*)(sm + MO_GB);

    const int tid  = threadIdx.x;
    const int lane = tid & 31;
    const int wid  = tid >> 5;                  // warp = gate index
    const int j0   = (blockIdx.x & 15) * LJ;    // 16 j-chunks of 16
    const int b0   = (blockIdx.x >> 4) * LB;    // 8 b-chunks of 16

    // ---- stage W hi/lo once. A row = gate*16 + jl (64 rows), K=256 ----
    {
        int row   = tid >> 1;                   // 0..63
        int khalf = (tid & 1) * 128;
        int wrow  = (row >> 4) * HQ + j0 + (row & 15);
        const float4* ws = (const float4*)(whh + (size_t)wrow * HQ + khalf);
#pragma unroll 8
        for (int q = 0; q < 32; ++q) {
            float4 v = ws[q];
            __nv_bfloat16 h0 = __float2bfloat16_rn(v.x), h1 = __float2bfloat16_rn(v.y);
            __nv_bfloat16 h2 = __float2bfloat16_rn(v.z), h3 = __float2bfloat16_rn(v.w);
            float l0 = v.x - __bfloat162float(h0), l1 = v.y - __bfloat162float(h1);
            float l2 = v.z - __bfloat162float(h2), l3 = v.w - __bfloat162float(h3);
            __nv_bfloat162 t0(h0, h1), t1(h2, h3);
            int k = khalf + q * 4;
            unsigned oa = sb + MO_AHI + aw_off(row, k);
            stsv2(oa, *(unsigned*)&t0, *(unsigned*)&t1);
            stsv2(oa + (MO_ALO - MO_AHI), pk2(l0, l1), pk2(l2, l3));
        }
    }
    __syncthreads();

    // activation items: item = tid + 128*i -> jl = tid&15, b = (tid>>4) + 8*i
    const int jl = tid & 15;
    const int bA = tid >> 4;                    // + 8*i
    float cst[2] = {0.f, 0.f};

    // h staging: row = tid>>3 (16 batches), kb = (tid&7)*32
    const int hrow = tid >> 3;
    const int hkb  = (tid & 7) * 32;

    // ldsm addressing (per warp)
    const int arow = wid * 16 + (lane & 15);
    const int brow = lane & 15;
    const int klo  = (lane >> 4) << 3;

    for (int t = 0; t < TQ; ++t) {
        const int rbuf = t & 1, wbuf = rbuf ^ 1;

        // prefetch xg_t: coalesced per gate (consumed after the mma loop)
        float xv[2][4];
#pragma unroll
        for (int i = 0; i < 2; ++i) {
            const float* p = xg + (((size_t)(b0 + bA + 8 * i) * TQ + t) * GQ) + j0 + jl;
#pragma unroll
            for (int g = 0; g < 4; ++g) xv[i][g] = __ldcg(p + (g << 8));
        }

        // stage h -> B hi/lo tiles (16 x 256 bf16, swizzled)
        {
            const float4* hs = (const float4*)(&g_hcur[rbuf][(b0 + hrow) * HQ + hkb]);
#pragma unroll
            for (int q = 0; q < 8; ++q) {
                float4 v = __ldcg(hs + q);
                __nv_bfloat16 h0 = __float2bfloat16_rn(v.x), h1 = __float2bfloat16_rn(v.y);
                __nv_bfloat16 h2 = __float2bfloat16_rn(v.z), h3 = __float2bfloat16_rn(v.w);
                float l0 = v.x - __bfloat162float(h0), l1 = v.y - __bfloat162float(h1);
                float l2 = v.z - __bfloat162float(h2), l3 = v.w - __bfloat162float(h3);
                __nv_bfloat162 t0(h0, h1), t1(h2, h3);
                int k = hkb + q * 4;
                unsigned ob = sb + MO_BHI + bw_off(hrow, k);
                stsv2(ob, *(unsigned*)&t0, *(unsigned*)&t1);
                stsv2(ob + (MO_BLO - MO_BHI), pk2(l0, l1), pk2(l2, l3));
            }
        }
        __syncthreads();

        // ---- D[64 x 16] = W x h^T : per warp 1 m-tile x 2 n-tiles, K=256 ----
        float acc[2][4];
#pragma unroll
        for (int nt = 0; nt < 2; ++nt)
#pragma unroll
            for (int e = 0; e < 4; ++e) acc[nt][e] = 0.f;

#pragma unroll
        for (int k16 = 0; k16 < 256; k16 += 16) {
            int kk = k16 + klo;
            unsigned ka = sb + MO_AHI + aw_off(arow, kk);
            unsigned kb2 = sb + MO_BHI + bw_off(brow, kk);
            unsigned ah[4], al[4], bh[4], bl[4];
            ldsm4(ah, ka);
            ldsm4(al, ka + (MO_ALO - MO_AHI));
            ldsm4(bh, kb2);
            ldsm4(bl, kb2 + (MO_BLO - MO_BHI));
            mma16816(acc[0], ah, bh[0], bh[2]);
            mma16816(acc[0], ah, bl[0], bl[2]);
            mma16816(acc[0], al, bh[0], bh[2]);
            mma16816(acc[1], ah, bh[1], bh[3]);
            mma16816(acc[1], ah, bl[1], bl[3]);
            mma16816(acc[1], al, bh[1], bh[3]);
        }

        // scatter accumulators to gate buffer [64 gates-rows][18 pad][batch]
        {
            int rowA = wid * 16 + (lane >> 2);
            int c0   = 2 * (lane & 3);
#pragma unroll
            for (int nt = 0; nt < 2; ++nt) {
                *(float2*)&gb[rowA * 18 + nt * 8 + c0]       = make_float2(acc[nt][0], acc[nt][1]);
                *(float2*)&gb[(rowA + 8) * 18 + nt * 8 + c0] = make_float2(acc[nt][2], acc[nt][3]);
            }
        }
        __syncthreads();

        // activation + state update (2 items per thread)
#pragma unroll
        for (int i = 0; i < 2; ++i) {
            int b = bA + 8 * i;
            float pi = gb[(jl     ) * 18 + b] + xv[i][0];
            float pf = gb[(16 + jl) * 18 + b] + xv[i][1];
            float pg = gb[(32 + jl) * 18 + b] + xv[i][2];
            float po = gb[(48 + jl) * 18 + b] + xv[i][3];
            float gi = sigf(pi), gf = sigf(pf), gg = tanhf_(pg), go = sigf(po);
            float cn = gf * cst[i] + gi * gg;
            cst[i] = cn;
            float hn = go * tanhf_(cn);
            int bg = b0 + b, jg = j0 + jl;
            g_hcur[wbuf][bg * HQ + jg] = hn;
            hseq[((size_t)bg * TQ + t) * HQ + jg] = hn;
            if (t == TQ - 1) { outh[bg * HQ + jg] = hn; outc[bg * HQ + jg] = cn; }
        }

        // grid barrier: syncthreads -> tid0 release-add + acquire-spin
        __syncthreads();
        if (tid == 0) {
            unsigned old;
            asm volatile("atom.release.gpu.global.add.u32 %0, [%1], 1;"
                         : "=r"(old) : "l"(&g_bar) : "memory");
            unsigned tgt = (unsigned)LGRID * (unsigned)(t + 1);
            unsigned v;
            do {
                asm volatile("ld.acquire.gpu.global.u32 %0, [%1];"
                             : "=r"(v) : "l"(&g_bar) : "memory");
            } while (v < tgt);
        }
        __syncthreads();
    }
}

// ---------------- launch -----------------------------------------------------
#define GEMM_SMEM (4 * TILE_B)

extern "C" void kernel_launch(void* const* d_in, const int* in_sizes, int n_in,
                              void* d_out, int out_size)
{
    const float* x    = (const float*)d_in[0];
    const float* wih0 = (const float*)d_in[1];
    const float* whh0 = (const float*)d_in[2];
    const float* bih0 = (const float*)d_in[3];
    const float* bhh0 = (const float*)d_in[4];
    const float* wih1 = (const float*)d_in[5];
    const float* whh1 = (const float*)d_in[6];
    const float* bih1 = (const float*)d_in[7];
    const float* bhh1 = (const float*)d_in[8];
    const float* wlin = (const float*)d_in[9];
    const float* blin = (const float*)d_in[10];

    float* out  = (float*)d_out;                    // [B,T,In]
    float* outh = out + (size_t)BQ * TQ * INQ;      // [2,B,H]
    float* outc = outh + 2 * BQ * HQ;               // [2,B,H]

    float *p_xg, *p_hseq;
    cudaGetSymbolAddress((void**)&p_xg,   g_xg);
    cudaGetSymbolAddress((void**)&p_hseq, g_hseq);
    cudaFuncSetAttribute(gemm3bf16, cudaFuncAttributeMaxDynamicSharedMemorySize, GEMM_SMEM);
    cudaFuncSetAttribute(lstm_mma,  cudaFuncAttributeMaxDynamicSharedMemorySize, LSTM_SMEM_MMA);

    dim3 gg(GQ / 128, MROWS / 128);    // (8, 1024)
    dim3 gf(INQ / 128, MROWS / 128);   // (1, 1024)

    // layer 0
    init_kernel<<<64, 256>>>();
    gemm3bf16<<<gg, 256, GEMM_SMEM>>>(x, wih0, bih0, bhh0, p_xg, MROWS, GQ, INQ);
    lstm_mma<<<LGRID, 128, LSTM_SMEM_MMA>>>(p_xg, whh0, p_hseq, outh, outc);
    // layer 1
    init_kernel<<<64, 256>>>();
    gemm3bf16<<<gg, 256, GEMM_SMEM>>>(p_hseq, wih1, bih1, bhh1, p_xg, MROWS, GQ, HQ);
    lstm_mma<<<LGRID, 128, LSTM_SMEM_MMA>>>(p_xg, whh1, p_hseq, outh + BQ * HQ, outc + BQ * HQ);
    // final projection
    gemm3bf16<<<gf, 256, GEMM_SMEM>>>(p_hseq, wlin, blin, nullptr, out, MROWS, INQ, HQ);
}